// round 4
// baseline (speedup 1.0000x reference)
#include <cuda_runtime.h>

// SegGPS_66949950210076
// out[b] = sum_m prod_l eps[idx[b,l], m, l, nup[b,l], ndn[b,l]]
// B=8192, L=64, M=64, LOCAL_DIM=4, eps (4,64,64,65,65) fp32.
//
// R4: worklist-driven transpose. flag_kernel marks touched cells AND builds
// a compact list of touched rows (l,nup,idx). transpose runs one CTA per
// listed row (fixed upper-bound grid 8320, early-out on i>=cnt), re-laying
// touched cells into T[cell][idx][m] (m contiguous 256B, L2-resident).
// Gather: warp per batch, float2 per lane.

#define B_SZ   8192
#define L_SZ   64
#define IDX_STRIDE 17305600   // M*L*65*65
#define M_STRIDE   270400     // L*65*65
#define L_STRIDE   4225       // 65*65
#define CELLS  89440          // sum_{k=1..64} k^2
#define T_ELEMS (CELLS * 256)
#define N_ROWS 8320           // sum_{l}(l+1) * 4 = 2080*4

__device__ float         g_T[T_ELEMS];        // 91.6 MB scratch (static)
__device__ unsigned char g_flags[4][CELLS];   // touched-cell flags
__device__ int           g_rowflag[N_ROWS];
__device__ int           g_rowlist[N_ROWS];
__device__ int           g_cnt;
__device__ int           g_is_int64;

__device__ __forceinline__ int cell_off(int l) {
    return l * (l + 1) * (2 * l + 1) / 6;     // sum_{j=1..l} j^2
}
__device__ __forceinline__ int tri_off(int l) { return l * (l + 1) / 2; }

// ---- clear flags + rowflags + counter, and detect index dtype ----
// Indices are logically int64 (ref) but JAX x64-off emits int32. Under int64
// LE every odd 32-bit word is 0 (values < 4); under int32 that is impossible
// over 262k random samples. Scan only the first n words (in-bounds either way).
__global__ __launch_bounds__(256) void prep_kernel(const unsigned* __restrict__ w,
                                                   int n_pairs) {
    int i = blockIdx.x * blockDim.x + threadIdx.x;
    if (i < CELLS) ((unsigned*)g_flags)[i] = 0u;       // 4*CELLS bytes
    if (i < N_ROWS) g_rowflag[i] = 0;
    if (i == 0) { g_cnt = 0; g_is_int64 = 1; }
    if (i < n_pairs && w[2 * i + 1] != 0u) g_is_int64 = 0;
}

// Per-warp scan of one batch: two ballots cover all 64 sites.
__device__ __forceinline__ void scan_batch(
    const void* idx_raw, int b, int lane,
    int& v0, int& v1, int& nup0, int& ndn0, int& nup1, int& ndn1)
{
    if (g_is_int64) {
        const long long* p = (const long long*)idx_raw + (size_t)b * L_SZ;
        v0 = (int)p[lane];  v1 = (int)p[lane + 32];
    } else {
        const int* p = (const int*)idx_raw + b * L_SZ;
        v0 = p[lane];  v1 = p[lane + 32];
    }
    unsigned bu0 = __ballot_sync(0xffffffffu, v0 & 1);
    unsigned bd0 = __ballot_sync(0xffffffffu, v0 & 2);
    unsigned bu1 = __ballot_sync(0xffffffffu, v1 & 1);
    unsigned bd1 = __ballot_sync(0xffffffffu, v1 & 2);
    unsigned mlt = (1u << lane) - 1u;
    nup0 = __popc(bu0 & mlt);               ndn0 = __popc(bd0 & mlt);
    nup1 = __popc(bu0) + __popc(bu1 & mlt); ndn1 = __popc(bd0) + __popc(bd1 & mlt);
}

__device__ __forceinline__ void mark(int l, int nup, int ndn, int v) {
    int cell = cell_off(l) + nup * (l + 1) + ndn;
    g_flags[v][cell] = 1;
    int rid = (tri_off(l) + nup) * 4 + v;
    if (g_rowflag[rid] == 0) {                       // cheap pre-filter
        if (atomicExch(&g_rowflag[rid], 1) == 0) {
            int p = atomicAdd(&g_cnt, 1);
            g_rowlist[p] = rid;
        }
    }
}

// ---- mark touched cells + build row worklist ----
__global__ __launch_bounds__(256) void flag_kernel(const void* __restrict__ idx_raw) {
    int lane = threadIdx.x & 31;
    int b = blockIdx.x * 8 + (threadIdx.x >> 5);
    int v0, v1, nu0, nd0, nu1, nd1;
    scan_batch(idx_raw, b, lane, v0, v1, nu0, nd0, nu1, nd1);
    mark(lane,      nu0, nd0, v0);
    mark(lane + 32, nu1, nd1, v1);
}

// ---- transpose: one CTA per listed row (l, nup, idx) ----
__global__ __launch_bounds__(256) void transpose_kernel(const float* __restrict__ eps) {
    const int i = blockIdx.x;
    if (i >= g_cnt) return;                   // one broadcast L2 read

    const int rid = g_rowlist[i];
    const int idx = rid & 3;
    const int row_tri = rid >> 2;
    // invert l(l+1)/2 <= row_tri
    int l = (int)((sqrtf(8.f * row_tri + 1.f) - 1.f) * 0.5f);
    while (tri_off(l + 1) <= row_tri) l++;
    while (tri_off(l)     >  row_tri) l--;
    const int nup = row_tri - tri_off(l);
    const int nv = l + 1;

    __shared__ float         sm[64][65];
    __shared__ unsigned char sflag[64];

    const int tid = threadIdx.x;
    const int c  = tid & 63;      // read phase: ndn ; write phase: m
    const int r4 = tid >> 6;

    if (r4 == 0) sflag[c] = (c < nv) ? g_flags[idx][cell_off(l) + nup * nv + c] : 0;
    __syncthreads();

    const float* src = eps + idx * IDX_STRIDE + l * L_STRIDE + nup * 65;
    if (c < nv && sflag[c]) {
        #pragma unroll
        for (int mb = 0; mb < 64; mb += 4) {
            int m = mb + r4;
            sm[m][c] = src[m * M_STRIDE + c];     // coalesced along flagged ndn
        }
    }
    __syncthreads();

    float* dst = g_T + (cell_off(l) + nup * nv) * 256 + idx * 64;
    #pragma unroll
    for (int nb = 0; nb < 64; nb += 4) {
        int ndn = nb + r4;
        if (ndn < nv && sflag[ndn])
            dst[ndn * 256 + c] = sm[c][ndn];      // 256B coalesced
    }
}

// ---- gather: warp per batch, float2 per lane (m = 2*lane, 2*lane+1) ----
__global__ __launch_bounds__(256) void seggps_kernel(
    const void* __restrict__ idx_raw,
    float*      __restrict__ out)
{
    __shared__ int soffs[8][64];

    const int lane = threadIdx.x & 31;
    const int w    = threadIdx.x >> 5;
    const int b    = blockIdx.x * 8 + w;

    int v0, v1, nu0, nd0, nu1, nd1;
    scan_batch(idx_raw, b, lane, v0, v1, nu0, nd0, nu1, nd1);
    int c0 = cell_off(lane)      + nu0 * (lane + 1)  + nd0;
    int c1 = cell_off(lane + 32) + nu1 * (lane + 33) + nd1;
    soffs[w][lane]      = c0 * 256 + v0 * 64;
    soffs[w][lane + 32] = c1 * 256 + v1 * 64;
    __syncwarp();

    float p0x = 1.f, p0y = 1.f, p1x = 1.f, p1y = 1.f;
    float p2x = 1.f, p2y = 1.f, p3x = 1.f, p3y = 1.f;
    #pragma unroll
    for (int l = 0; l < L_SZ; l += 4) {
        float2 a  = __ldg((const float2*)(g_T + soffs[w][l + 0]) + lane);
        float2 b2 = __ldg((const float2*)(g_T + soffs[w][l + 1]) + lane);
        float2 c  = __ldg((const float2*)(g_T + soffs[w][l + 2]) + lane);
        float2 d  = __ldg((const float2*)(g_T + soffs[w][l + 3]) + lane);
        p0x *= a.x;  p0y *= a.y;
        p1x *= b2.x; p1y *= b2.y;
        p2x *= c.x;  p2y *= c.y;
        p3x *= d.x;  p3y *= d.y;
    }
    float s = (p0x * p1x) * (p2x * p3x) + (p0y * p1y) * (p2y * p3y);

    #pragma unroll
    for (int o = 16; o; o >>= 1) s += __shfl_xor_sync(0xffffffffu, s, o);
    if (lane == 0) out[b] = s;
}

extern "C" void kernel_launch(void* const* d_in, const int* in_sizes, int n_in,
                              void* d_out, int out_size)
{
    const void*  idx = d_in[0];                 // indices (B,L) int32 or int64
    const float* eps = (const float*)d_in[1];   // epsilon fp32
    float* out = (float*)d_out;

    int n = in_sizes[0];                        // 524288
    int n_pairs = n / 2;
    int prep_n = (n_pairs > CELLS) ? n_pairs : CELLS;

    prep_kernel<<<(prep_n + 255) / 256, 256>>>((const unsigned*)idx, n_pairs);
    flag_kernel<<<B_SZ / 8, 256>>>(idx);
    transpose_kernel<<<N_ROWS, 256>>>(eps);
    seggps_kernel<<<B_SZ / 8, 256>>>(idx, out);
}